// round 14
// baseline (speedup 1.0000x reference)
#include <cuda_runtime.h>
#include <cuda_bf16.h>

// GCN: 4 layers, N=100000, dims 64->32->16->8->64, E=3,200,000.
// conv(y) = D^-1/2 Â D^-1/2 (y@W) + b,  Â = A + I.
// Factored: h' = (y@W)·dinv ; raw = Â h' ; z = raw·dinv + b.
// Layer 4 via linearity: out = (Â(relu(z3)·dinv))·dinv @ W4 + b4.
//
// GEMMs fused into agg epilogues. Epilogue weights are stored TRANSPOSED in
// smem (Wt[c][k], rows padded to 36 floats) so each lane reads its columns'
// weights as LDS.128 — cuts epilogue instruction count ~35% (measured issue
// competition was throttling the pull loop's memory issue rate).
//
// edge_index dtype detected on device (JAX silently downcasts int64->int32).

#define N_NODES 100000
#define N_EDGES 3200000
#define CAP     128      // max in-edges per node (deg~Poisson(32))

// ---------------- scratch (static device globals; no allocation) ----------------
__device__ __align__(16) int   g_csr[(size_t)N_NODES * CAP];
__device__ __align__(16) int   g_cnt[N_NODES];
__device__ int                 g_is_i32;
__device__ __align__(16) float g_bufA[N_NODES * 32];
__device__ __align__(16) float g_bufB[N_NODES * 32];

static inline int cdiv(long long a, int b) { return (int)((a + b - 1) / b); }

__device__ __forceinline__ float node_dinv(int n) {
    return rsqrtf((float)g_cnt[n] + 1.0f);   // +1 self loop
}

// ---------------- prep: cnt=0 + dtype detect ----------------
__global__ void init_detect_kernel(const long long* __restrict__ ei64) {
    unsigned i = blockIdx.x * blockDim.x + threadIdx.x;
    if (i < N_NODES) g_cnt[i] = 0;
    if (blockIdx.x == 0) {
        __shared__ int bad;
        if (threadIdx.x == 0) bad = 0;
        __syncthreads();
        for (int k = threadIdx.x; k < 2048; k += blockDim.x) {
            long long v = ei64[k];
            if (v < 0 || v >= N_NODES) bad = 1;   // benign race
        }
        __syncthreads();
        if (threadIdx.x == 0) g_is_i32 = bad;
    }
}

// ---------------- prep: bin edges into padded CSR (4 edges/thread) ----------
__global__ void prep_fill_kernel(const void* __restrict__ ei_raw) {
    unsigned t = blockIdx.x * blockDim.x + threadIdx.x;
    unsigned e0 = t * 4;
    if (e0 >= N_EDGES) return;
    int s[4], d[4];
    if (g_is_i32) {
        const int* ei = (const int*)ei_raw;
        int4 sv = *(const int4*)(ei + e0);
        int4 dv = *(const int4*)(ei + N_EDGES + e0);
        s[0]=sv.x; s[1]=sv.y; s[2]=sv.z; s[3]=sv.w;
        d[0]=dv.x; d[1]=dv.y; d[2]=dv.z; d[3]=dv.w;
    } else {
        const long long* ei = (const long long*)ei_raw;
#pragma unroll
        for (int q = 0; q < 4; q++) {
            s[q] = (int)ei[e0 + q];
            d[q] = (int)ei[N_EDGES + e0 + q];
        }
    }
#pragma unroll
    for (int q = 0; q < 4; q++) {
        int ss = s[q] & 0x7fffffff; if (ss >= N_NODES) ss %= N_NODES;
        int dd = d[q] & 0x7fffffff; if (dd >= N_NODES) dd %= N_NODES;
        int slot = atomicAdd(&g_cnt[dd], 1);
        if (slot < CAP) g_csr[(size_t)dd * CAP + slot] = ss;
    }
}

// ---------------- gemm1: h1' = (x@W1)·dinv  (64 -> 32, thread-per-node) -------
__global__ void gemm1_kernel(const float* __restrict__ in,
                             const float* __restrict__ W,
                             float* __restrict__ hout) {
    __shared__ float Ws[64 * 32];
    for (int i = threadIdx.x; i < 64 * 32; i += blockDim.x) Ws[i] = W[i];
    __syncthreads();

    int node = blockIdx.x * blockDim.x + threadIdx.x;
    if (node >= N_NODES) return;
    float dinv = node_dinv(node);

    float4 s4[8];
#pragma unroll
    for (int q = 0; q < 8; q++) s4[q] = make_float4(0.f, 0.f, 0.f, 0.f);

    const float4* row = (const float4*)(in + (size_t)node * 64);
    const float4* W4p = (const float4*)Ws;
#pragma unroll
    for (int c = 0; c < 16; c++) {
        float4 r = row[c];
        float a[4] = {r.x, r.y, r.z, r.w};
#pragma unroll
        for (int q = 0; q < 4; q++) {
            int k = 4 * c + q;
            float av = a[q];
#pragma unroll
            for (int j = 0; j < 8; j++) {
                float4 w = W4p[k * 8 + j];
                s4[j].x = fmaf(av, w.x, s4[j].x);
                s4[j].y = fmaf(av, w.y, s4[j].y);
                s4[j].z = fmaf(av, w.z, s4[j].z);
                s4[j].w = fmaf(av, w.w, s4[j].w);
            }
        }
    }
    float4* outv = (float4*)(hout + (size_t)node * 32);
#pragma unroll
    for (int q = 0; q < 8; q++) {
        s4[q].x *= dinv; s4[q].y *= dinv; s4[q].z *= dinv; s4[q].w *= dinv;
        outv[q] = s4[q];
    }
}

// ---------------- shared agg core: raw = h[node] + sum h[src] ----------------
template <int TPE>
__device__ __forceinline__ float4 agg_pull(const float4* __restrict__ h,
                                           int node, int j) {
    float4 acc = h[(size_t)node * TPE + j];        // self loop
    int n = g_cnt[node];
    if (n > CAP) n = CAP;
    const int* lst = g_csr + (size_t)node * CAP;   // 16B aligned
    int i = 0;
    for (; i + 4 <= n; i += 4) {
        int4 a4 = *(const int4*)(lst + i);
        float4 v0 = h[(size_t)a4.x * TPE + j];
        float4 v1 = h[(size_t)a4.y * TPE + j];
        float4 v2 = h[(size_t)a4.z * TPE + j];
        float4 v3 = h[(size_t)a4.w * TPE + j];
        acc.x += (v0.x + v1.x) + (v2.x + v3.x);
        acc.y += (v0.y + v1.y) + (v2.y + v3.y);
        acc.z += (v0.z + v1.z) + (v2.z + v3.z);
        acc.w += (v0.w + v1.w) + (v2.w + v3.w);
    }
    for (; i < n; i++) {
        int s = __ldg(&lst[i]);
        float4 v = h[(size_t)s * TPE + j];
        acc.x += v.x; acc.y += v.y; acc.z += v.z; acc.w += v.w;
    }
    return acc;
}

// ---- agg32 + gemm2: h2' = relu(Agg(h1')·dinv + b1)@W2 · dinv  (-> 16-dim) ----
// Wt[c][k] transposed, rows padded to 36 floats (9 float4) for aligned LDS.128.
__global__ void agg_gemm2_kernel(const float4* __restrict__ h,
                                 float* __restrict__ h2,
                                 const float* __restrict__ b1,
                                 const float* __restrict__ W2) {
    __shared__ float Wt[16 * 36];                  // [c][k], pad 36
    __shared__ float bs[32];
    __shared__ float4 zsm[256];
    for (int i = threadIdx.x; i < 32 * 16; i += blockDim.x) {
        int k = i >> 4, c = i & 15;                // W2 row-major [k][c]
        Wt[c * 36 + k] = W2[i];
    }
    if (threadIdx.x < 32) bs[threadIdx.x] = b1[threadIdx.x];
    __syncthreads();

    unsigned gid = blockIdx.x * blockDim.x + threadIdx.x;
    if (gid >= (unsigned)N_NODES * 8) return;      // 800000 % 256 == 0
    int node = gid >> 3;
    int j    = gid & 7;

    float4 acc = agg_pull<8>(h, node, j);
    float dinv = node_dinv(node);
    float4 z;
    z.x = fmaxf(fmaf(acc.x, dinv, bs[4 * j + 0]), 0.f);
    z.y = fmaxf(fmaf(acc.y, dinv, bs[4 * j + 1]), 0.f);
    z.z = fmaxf(fmaf(acc.z, dinv, bs[4 * j + 2]), 0.f);
    z.w = fmaxf(fmaf(acc.w, dinv, bs[4 * j + 3]), 0.f);

    zsm[threadIdx.x] = z;                          // STS.128
    __syncwarp();

    int gbase = threadIdx.x & ~7;
    int c0 = 2 * j, c1 = 2 * j + 1;
    const float4* w0 = (const float4*)(Wt + c0 * 36);   // 9 float4 per row
    const float4* w1 = (const float4*)(Wt + c1 * 36);
    float o0 = 0.f, o1 = 0.f;
#pragma unroll
    for (int g = 0; g < 8; g++) {
        float4 zb = zsm[gbase + g];                // broadcast LDS.128
        float4 a = w0[g];                          // LDS.128 (contig k)
        float4 b = w1[g];
        o0 = fmaf(zb.x, a.x, o0); o0 = fmaf(zb.y, a.y, o0);
        o0 = fmaf(zb.z, a.z, o0); o0 = fmaf(zb.w, a.w, o0);
        o1 = fmaf(zb.x, b.x, o1); o1 = fmaf(zb.y, b.y, o1);
        o1 = fmaf(zb.z, b.z, o1); o1 = fmaf(zb.w, b.w, o1);
    }
    *(float2*)(h2 + (size_t)node * 16 + c0) = make_float2(o0 * dinv, o1 * dinv);
}

// ---- agg16 + gemm3: h3' = relu(Agg(h2')·dinv + b2)@W3 · dinv  (-> 8-dim) ----
__global__ void agg_gemm3_kernel(const float4* __restrict__ h,
                                 float* __restrict__ h3,
                                 const float* __restrict__ b2,
                                 const float* __restrict__ W3) {
    __shared__ float Wt[8 * 20];                   // [c][k], pad 20 (5 float4)
    __shared__ float bs[16];
    __shared__ float4 zsm[256];
    for (int i = threadIdx.x; i < 16 * 8; i += blockDim.x) {
        int k = i >> 3, c = i & 7;                 // W3 row-major [k][c]
        Wt[c * 20 + k] = W3[i];
    }
    if (threadIdx.x < 16) bs[threadIdx.x] = b2[threadIdx.x];
    __syncthreads();

    unsigned gid = blockIdx.x * blockDim.x + threadIdx.x;
    if (gid >= (unsigned)N_NODES * 4) return;      // 400000 % 32 == 0
    int node = gid >> 2;
    int j    = gid & 3;

    float4 acc = agg_pull<4>(h, node, j);
    float dinv = node_dinv(node);
    float4 z;
    z.x = fmaxf(fmaf(acc.x, dinv, bs[4 * j + 0]), 0.f);
    z.y = fmaxf(fmaf(acc.y, dinv, bs[4 * j + 1]), 0.f);
    z.z = fmaxf(fmaf(acc.z, dinv, bs[4 * j + 2]), 0.f);
    z.w = fmaxf(fmaf(acc.w, dinv, bs[4 * j + 3]), 0.f);

    zsm[threadIdx.x] = z;
    __syncwarp();

    int gbase = threadIdx.x & ~3;
    int c0 = 2 * j, c1 = 2 * j + 1;
    const float4* w0 = (const float4*)(Wt + c0 * 20);   // 5 float4 per row
    const float4* w1 = (const float4*)(Wt + c1 * 20);
    float o0 = 0.f, o1 = 0.f;
#pragma unroll
    for (int g = 0; g < 4; g++) {
        float4 zb = zsm[gbase + g];
        float4 a = w0[g];
        float4 b = w1[g];
        o0 = fmaf(zb.x, a.x, o0); o0 = fmaf(zb.y, a.y, o0);
        o0 = fmaf(zb.z, a.z, o0); o0 = fmaf(zb.w, a.w, o0);
        o1 = fmaf(zb.x, b.x, o1); o1 = fmaf(zb.y, b.y, o1);
        o1 = fmaf(zb.z, b.z, o1); o1 = fmaf(zb.w, b.w, o1);
    }
    *(float2*)(h3 + (size_t)node * 8 + c0) = make_float2(o0 * dinv, o1 * dinv);
}

// ---- agg8 + seed: h4' = relu(Agg(h3')·dinv + b3) · dinv  (-> 8-dim) ----
__global__ void agg_seed_kernel(const float4* __restrict__ h,
                                float4* __restrict__ h4,
                                const float* __restrict__ b3) {
    unsigned gid = blockIdx.x * blockDim.x + threadIdx.x;
    if (gid >= (unsigned)N_NODES * 2) return;      // 200000 % 32 == 0
    int node = gid >> 1;
    int j    = gid & 1;

    float4 acc = agg_pull<2>(h, node, j);
    float dinv = node_dinv(node);
    float4 bv = *(const float4*)(b3 + 4 * j);
    float4 o;
    o.x = fmaxf(fmaf(acc.x, dinv, bv.x), 0.f) * dinv;
    o.y = fmaxf(fmaf(acc.y, dinv, bv.y), 0.f) * dinv;
    o.z = fmaxf(fmaf(acc.z, dinv, bv.z), 0.f) * dinv;
    o.w = fmaxf(fmaf(acc.w, dinv, bv.w), 0.f) * dinv;
    h4[gid] = o;
}

// ---- agg8 + gemm4: out = (Agg(h4')·dinv)@W4 + b4  (-> 64-dim, d_out) ----
__global__ void agg_final_kernel(const float4* __restrict__ h,
                                 float* __restrict__ out,
                                 const float* __restrict__ W4,
                                 const float* __restrict__ b4) {
    __shared__ float Ws[8 * 64];
    __shared__ float bs[64];
    __shared__ float4 zsm[256];
    for (int i = threadIdx.x; i < 8 * 64; i += blockDim.x) Ws[i] = W4[i];
    if (threadIdx.x < 64) bs[threadIdx.x] = b4[threadIdx.x];
    __syncthreads();

    unsigned gid = blockIdx.x * blockDim.x + threadIdx.x;
    if (gid >= (unsigned)N_NODES * 2) return;      // warp-uniform
    int node = gid >> 1;
    int j    = gid & 1;

    float4 acc = agg_pull<2>(h, node, j);
    float dinv = node_dinv(node);
    float4 z;
    z.x = acc.x * dinv; z.y = acc.y * dinv; z.z = acc.z * dinv; z.w = acc.w * dinv;

    zsm[threadIdx.x] = z;
    __syncwarp();

    int gbase = threadIdx.x & ~1;
    float4 z0 = zsm[gbase + 0];                     // k = 0..3
    float4 z1 = zsm[gbase + 1];                     // k = 4..7
    float zf[8] = {z0.x, z0.y, z0.z, z0.w, z1.x, z1.y, z1.z, z1.w};

    int cbase = 32 * j;                             // lane j: cols [32j, 32j+32)
    float4 s4[8];
    const float4* bsv = (const float4*)(bs + cbase);
#pragma unroll
    for (int q = 0; q < 8; q++) s4[q] = bsv[q];

#pragma unroll
    for (int k = 0; k < 8; k++) {
        float av = zf[k];
        const float4* wrow = (const float4*)(Ws + k * 64 + cbase);
#pragma unroll
        for (int q = 0; q < 8; q++) {
            float4 w = wrow[q];
            s4[q].x = fmaf(av, w.x, s4[q].x);
            s4[q].y = fmaf(av, w.y, s4[q].y);
            s4[q].z = fmaf(av, w.z, s4[q].z);
            s4[q].w = fmaf(av, w.w, s4[q].w);
        }
    }
    float4* outv = (float4*)(out + (size_t)node * 64 + cbase);
#pragma unroll
    for (int q = 0; q < 8; q++) outv[q] = s4[q];
}

// ---------------- launch ----------------
extern "C" void kernel_launch(void* const* d_in, const int* in_sizes, int n_in,
                              void* d_out, int out_size) {
    const float* x  = (const float*)d_in[0];
    const float* W1 = (const float*)d_in[2];
    const float* b1 = (const float*)d_in[3];
    const float* W2 = (const float*)d_in[4];
    const float* b2 = (const float*)d_in[5];
    const float* W3 = (const float*)d_in[6];
    const float* b3 = (const float*)d_in[7];
    const float* W4 = (const float*)d_in[8];
    const float* b4 = (const float*)d_in[9];
    float* out = (float*)d_out;

    float *A, *B;
    cudaGetSymbolAddress((void**)&A, g_bufA);
    cudaGetSymbolAddress((void**)&B, g_bufB);
    float4* A4 = (float4*)A;
    float4* B4 = (float4*)B;

    const int T = 256;

    // prep
    init_detect_kernel<<<cdiv(N_NODES, T), T>>>((const long long*)d_in[1]);
    prep_fill_kernel<<<cdiv(N_EDGES / 4, T), T>>>(d_in[1]);

    // conv1 gemm: A = (x@W1)·dinv   (32-dim)
    gemm1_kernel<<<cdiv(N_NODES, 128), 128>>>(x, W1, A);
    // conv1 agg + conv2 gemm: B = h2'  (16-dim)
    agg_gemm2_kernel<<<cdiv((long long)N_NODES * 8, T), T>>>(A4, B, b1, W2);
    // conv2 agg + conv3 gemm: A = h3'  (8-dim)
    agg_gemm3_kernel<<<cdiv((long long)N_NODES * 4, T), T>>>(B4, A, b2, W3);
    // conv3 agg + relu seed:  B = h4'  (8-dim)
    agg_seed_kernel<<<cdiv((long long)N_NODES * 2, T), T>>>(A4, B4, b3);
    // conv4 agg + final gemm: out      (64-dim)
    agg_final_kernel<<<cdiv((long long)N_NODES * 2, T), T>>>(B4, out, W4, b4);
}

// round 15
// speedup vs baseline: 1.0769x; 1.0769x over previous
#include <cuda_runtime.h>
#include <cuda_bf16.h>
#include <cuda_fp16.h>

// GCN: 4 layers, N=100000, dims 64->32->16->8->64, E=3,200,000.
// conv(y) = D^-1/2 Â D^-1/2 (y@W) + b,  Â = A + I.
// Factored: h' = (y@W)·dinv ; raw = Â h' ; z = raw·dinv + b.
// Layer 4 via linearity: out = (Â(relu(z3)·dinv))·dinv @ W4 + b4.
//
// h1' and h2' (gather sources of the two largest aggregations) are stored
// fp16 (halving the dominant L2 gather traffic); accumulation stays fp32.
// h3'/h4' remain fp32. Epilogues use the R12 SMEM-staging + scalar-Ws form
// (transposed-LDS.128 variant measured as a regression).
//
// edge_index dtype detected on device (JAX silently downcasts int64->int32).

#define N_NODES 100000
#define N_EDGES 3200000
#define CAP     128      // max in-edges per node (deg~Poisson(32))

// ---------------- scratch (static device globals; no allocation) ----------------
__device__ __align__(16) int   g_csr[(size_t)N_NODES * CAP];
__device__ __align__(16) int   g_cnt[N_NODES];
__device__ int                 g_is_i32;
__device__ __align__(16) float g_bufA[N_NODES * 32];
__device__ __align__(16) float g_bufB[N_NODES * 32];

static inline int cdiv(long long a, int b) { return (int)((a + b - 1) / b); }

__device__ __forceinline__ float node_dinv(int n) {
    return rsqrtf((float)g_cnt[n] + 1.0f);   // +1 self loop
}

// ---------------- prep: cnt=0 + dtype detect ----------------
__global__ void init_detect_kernel(const long long* __restrict__ ei64) {
    unsigned i = blockIdx.x * blockDim.x + threadIdx.x;
    if (i < N_NODES) g_cnt[i] = 0;
    if (blockIdx.x == 0) {
        __shared__ int bad;
        if (threadIdx.x == 0) bad = 0;
        __syncthreads();
        for (int k = threadIdx.x; k < 2048; k += blockDim.x) {
            long long v = ei64[k];
            if (v < 0 || v >= N_NODES) bad = 1;   // benign race
        }
        __syncthreads();
        if (threadIdx.x == 0) g_is_i32 = bad;
    }
}

// ---------------- prep: bin edges into padded CSR (4 edges/thread) ----------
__global__ void prep_fill_kernel(const void* __restrict__ ei_raw) {
    unsigned t = blockIdx.x * blockDim.x + threadIdx.x;
    unsigned e0 = t * 4;
    if (e0 >= N_EDGES) return;
    int s[4], d[4];
    if (g_is_i32) {
        const int* ei = (const int*)ei_raw;
        int4 sv = *(const int4*)(ei + e0);
        int4 dv = *(const int4*)(ei + N_EDGES + e0);
        s[0]=sv.x; s[1]=sv.y; s[2]=sv.z; s[3]=sv.w;
        d[0]=dv.x; d[1]=dv.y; d[2]=dv.z; d[3]=dv.w;
    } else {
        const long long* ei = (const long long*)ei_raw;
#pragma unroll
        for (int q = 0; q < 4; q++) {
            s[q] = (int)ei[e0 + q];
            d[q] = (int)ei[N_EDGES + e0 + q];
        }
    }
#pragma unroll
    for (int q = 0; q < 4; q++) {
        int ss = s[q] & 0x7fffffff; if (ss >= N_NODES) ss %= N_NODES;
        int dd = d[q] & 0x7fffffff; if (dd >= N_NODES) dd %= N_NODES;
        int slot = atomicAdd(&g_cnt[dd], 1);
        if (slot < CAP) g_csr[(size_t)dd * CAP + slot] = ss;
    }
}

// ---------------- gemm1: h1' = (x@W1)·dinv  (64 -> 32, fp16 out) ----------
__global__ void gemm1_kernel(const float* __restrict__ in,
                             const float* __restrict__ W,
                             __half2* __restrict__ hout) {
    __shared__ float Ws[64 * 32];
    for (int i = threadIdx.x; i < 64 * 32; i += blockDim.x) Ws[i] = W[i];
    __syncthreads();

    int node = blockIdx.x * blockDim.x + threadIdx.x;
    if (node >= N_NODES) return;
    float dinv = node_dinv(node);

    float4 s4[8];
#pragma unroll
    for (int q = 0; q < 8; q++) s4[q] = make_float4(0.f, 0.f, 0.f, 0.f);

    const float4* row = (const float4*)(in + (size_t)node * 64);
    const float4* W4p = (const float4*)Ws;
#pragma unroll
    for (int c = 0; c < 16; c++) {
        float4 r = row[c];
        float a[4] = {r.x, r.y, r.z, r.w};
#pragma unroll
        for (int q = 0; q < 4; q++) {
            int k = 4 * c + q;
            float av = a[q];
#pragma unroll
            for (int j = 0; j < 8; j++) {
                float4 w = W4p[k * 8 + j];
                s4[j].x = fmaf(av, w.x, s4[j].x);
                s4[j].y = fmaf(av, w.y, s4[j].y);
                s4[j].z = fmaf(av, w.z, s4[j].z);
                s4[j].w = fmaf(av, w.w, s4[j].w);
            }
        }
    }
    __half2 hb[16];
#pragma unroll
    for (int q = 0; q < 8; q++) {
        hb[2 * q]     = __floats2half2_rn(s4[q].x * dinv, s4[q].y * dinv);
        hb[2 * q + 1] = __floats2half2_rn(s4[q].z * dinv, s4[q].w * dinv);
    }
    uint4* o = (uint4*)(hout + (size_t)node * 16);
    const uint4* hv = (const uint4*)hb;
#pragma unroll
    for (int q = 0; q < 4; q++) o[q] = hv[q];
}

// ------------- agg core, fp16 rows: acc = Σ half4 chunks, fp32 accumulate ----
// U2PR = uint2 (4 halfs) per row. Lane j covers halfs [4j, 4j+4).
__device__ __forceinline__ void acc_h4(uint2 u, float4& a) {
    float2 f0 = __half22float2(*(__half2*)&u.x);
    float2 f1 = __half22float2(*(__half2*)&u.y);
    a.x += f0.x; a.y += f0.y; a.z += f1.x; a.w += f1.y;
}

template <int U2PR>
__device__ __forceinline__ float4 agg_pull_h(const uint2* __restrict__ h,
                                             int node, int j) {
    float4 acc = make_float4(0.f, 0.f, 0.f, 0.f);
    acc_h4(h[(size_t)node * U2PR + j], acc);       // self loop
    int n = g_cnt[node];
    if (n > CAP) n = CAP;
    const int* lst = g_csr + (size_t)node * CAP;
    int i = 0;
    for (; i + 4 <= n; i += 4) {
        int4 a4 = *(const int4*)(lst + i);
        uint2 u0 = h[(size_t)a4.x * U2PR + j];
        uint2 u1 = h[(size_t)a4.y * U2PR + j];
        uint2 u2 = h[(size_t)a4.z * U2PR + j];
        uint2 u3 = h[(size_t)a4.w * U2PR + j];
        acc_h4(u0, acc); acc_h4(u1, acc); acc_h4(u2, acc); acc_h4(u3, acc);
    }
    for (; i < n; i++) acc_h4(h[(size_t)__ldg(&lst[i]) * U2PR + j], acc);
    return acc;
}

// ------------- agg core, fp32 rows (unchanged) -------------
template <int TPE>
__device__ __forceinline__ float4 agg_pull(const float4* __restrict__ h,
                                           int node, int j) {
    float4 acc = h[(size_t)node * TPE + j];        // self loop
    int n = g_cnt[node];
    if (n > CAP) n = CAP;
    const int* lst = g_csr + (size_t)node * CAP;
    int i = 0;
    for (; i + 4 <= n; i += 4) {
        int4 a4 = *(const int4*)(lst + i);
        float4 v0 = h[(size_t)a4.x * TPE + j];
        float4 v1 = h[(size_t)a4.y * TPE + j];
        float4 v2 = h[(size_t)a4.z * TPE + j];
        float4 v3 = h[(size_t)a4.w * TPE + j];
        acc.x += (v0.x + v1.x) + (v2.x + v3.x);
        acc.y += (v0.y + v1.y) + (v2.y + v3.y);
        acc.z += (v0.z + v1.z) + (v2.z + v3.z);
        acc.w += (v0.w + v1.w) + (v2.w + v3.w);
    }
    for (; i < n; i++) {
        int s = __ldg(&lst[i]);
        float4 v = h[(size_t)s * TPE + j];
        acc.x += v.x; acc.y += v.y; acc.z += v.z; acc.w += v.w;
    }
    return acc;
}

// ---- agg32(fp16) + gemm2: h2' = relu(Agg(h1')·dinv + b1)@W2 · dinv (fp16) ----
__global__ void agg_gemm2_kernel(const uint2* __restrict__ h,
                                 __half* __restrict__ h2,
                                 const float* __restrict__ b1,
                                 const float* __restrict__ W2) {
    __shared__ float Ws[32 * 16];
    __shared__ float bs[32];
    __shared__ float4 zsm[256];
    for (int i = threadIdx.x; i < 32 * 16; i += blockDim.x) Ws[i] = W2[i];
    if (threadIdx.x < 32) bs[threadIdx.x] = b1[threadIdx.x];
    __syncthreads();

    unsigned gid = blockIdx.x * blockDim.x + threadIdx.x;
    if (gid >= (unsigned)N_NODES * 8) return;      // 800000 % 256 == 0
    int node = gid >> 3;
    int j    = gid & 7;

    float4 acc = agg_pull_h<8>(h, node, j);        // 64B rows: 8 uint2
    float dinv = node_dinv(node);
    float4 z;
    z.x = fmaxf(fmaf(acc.x, dinv, bs[4 * j + 0]), 0.f);
    z.y = fmaxf(fmaf(acc.y, dinv, bs[4 * j + 1]), 0.f);
    z.z = fmaxf(fmaf(acc.z, dinv, bs[4 * j + 2]), 0.f);
    z.w = fmaxf(fmaf(acc.w, dinv, bs[4 * j + 3]), 0.f);

    zsm[threadIdx.x] = z;                          // STS.128
    __syncwarp();

    int gbase = threadIdx.x & ~7;
    float o0 = 0.f, o1 = 0.f;
    int c0 = 2 * j, c1 = 2 * j + 1;
#pragma unroll
    for (int g = 0; g < 8; g++) {
        float4 zb = zsm[gbase + g];                // broadcast LDS.128
        int k = 4 * g;
        o0 = fmaf(zb.x, Ws[(k + 0) * 16 + c0], o0);
        o1 = fmaf(zb.x, Ws[(k + 0) * 16 + c1], o1);
        o0 = fmaf(zb.y, Ws[(k + 1) * 16 + c0], o0);
        o1 = fmaf(zb.y, Ws[(k + 1) * 16 + c1], o1);
        o0 = fmaf(zb.z, Ws[(k + 2) * 16 + c0], o0);
        o1 = fmaf(zb.z, Ws[(k + 2) * 16 + c1], o1);
        o0 = fmaf(zb.w, Ws[(k + 3) * 16 + c0], o0);
        o1 = fmaf(zb.w, Ws[(k + 3) * 16 + c1], o1);
    }
    *(__half2*)(h2 + (size_t)node * 16 + c0) =
        __floats2half2_rn(o0 * dinv, o1 * dinv);
}

// ---- agg16(fp16) + gemm3: h3' = relu(Agg(h2')·dinv + b2)@W3 · dinv (fp32) ----
__global__ void agg_gemm3_kernel(const uint2* __restrict__ h,
                                 float* __restrict__ h3,
                                 const float* __restrict__ b2,
                                 const float* __restrict__ W3) {
    __shared__ float Ws[16 * 8];
    __shared__ float bs[16];
    __shared__ float4 zsm[256];
    for (int i = threadIdx.x; i < 16 * 8; i += blockDim.x) Ws[i] = W3[i];
    if (threadIdx.x < 16) bs[threadIdx.x] = b2[threadIdx.x];
    __syncthreads();

    unsigned gid = blockIdx.x * blockDim.x + threadIdx.x;
    if (gid >= (unsigned)N_NODES * 4) return;      // 400000 % 32 == 0
    int node = gid >> 2;
    int j    = gid & 3;

    float4 acc = agg_pull_h<4>(h, node, j);        // 32B rows: 4 uint2
    float dinv = node_dinv(node);
    float4 z;
    z.x = fmaxf(fmaf(acc.x, dinv, bs[4 * j + 0]), 0.f);
    z.y = fmaxf(fmaf(acc.y, dinv, bs[4 * j + 1]), 0.f);
    z.z = fmaxf(fmaf(acc.z, dinv, bs[4 * j + 2]), 0.f);
    z.w = fmaxf(fmaf(acc.w, dinv, bs[4 * j + 3]), 0.f);

    zsm[threadIdx.x] = z;
    __syncwarp();

    int gbase = threadIdx.x & ~3;
    float o0 = 0.f, o1 = 0.f;
    int c0 = 2 * j, c1 = 2 * j + 1;
#pragma unroll
    for (int g = 0; g < 4; g++) {
        float4 zb = zsm[gbase + g];
        int k = 4 * g;
        o0 = fmaf(zb.x, Ws[(k + 0) * 8 + c0], o0);
        o1 = fmaf(zb.x, Ws[(k + 0) * 8 + c1], o1);
        o0 = fmaf(zb.y, Ws[(k + 1) * 8 + c0], o0);
        o1 = fmaf(zb.y, Ws[(k + 1) * 8 + c1], o1);
        o0 = fmaf(zb.z, Ws[(k + 2) * 8 + c0], o0);
        o1 = fmaf(zb.z, Ws[(k + 2) * 8 + c1], o1);
        o0 = fmaf(zb.w, Ws[(k + 3) * 8 + c0], o0);
        o1 = fmaf(zb.w, Ws[(k + 3) * 8 + c1], o1);
    }
    *(float2*)(h3 + (size_t)node * 8 + c0) = make_float2(o0 * dinv, o1 * dinv);
}

// ---- agg8 + seed: h4' = relu(Agg(h3')·dinv + b3) · dinv  (fp32) ----
__global__ void agg_seed_kernel(const float4* __restrict__ h,
                                float4* __restrict__ h4,
                                const float* __restrict__ b3) {
    unsigned gid = blockIdx.x * blockDim.x + threadIdx.x;
    if (gid >= (unsigned)N_NODES * 2) return;
    int node = gid >> 1;
    int j    = gid & 1;

    float4 acc = agg_pull<2>(h, node, j);
    float dinv = node_dinv(node);
    float4 bv = *(const float4*)(b3 + 4 * j);
    float4 o;
    o.x = fmaxf(fmaf(acc.x, dinv, bv.x), 0.f) * dinv;
    o.y = fmaxf(fmaf(acc.y, dinv, bv.y), 0.f) * dinv;
    o.z = fmaxf(fmaf(acc.z, dinv, bv.z), 0.f) * dinv;
    o.w = fmaxf(fmaf(acc.w, dinv, bv.w), 0.f) * dinv;
    h4[gid] = o;
}

// ---- agg8 + gemm4: out = (Agg(h4')·dinv)@W4 + b4  (-> 64-dim, d_out) ----
__global__ void agg_final_kernel(const float4* __restrict__ h,
                                 float* __restrict__ out,
                                 const float* __restrict__ W4,
                                 const float* __restrict__ b4) {
    __shared__ float Ws[8 * 64];
    __shared__ float bs[64];
    __shared__ float4 zsm[256];
    for (int i = threadIdx.x; i < 8 * 64; i += blockDim.x) Ws[i] = W4[i];
    if (threadIdx.x < 64) bs[threadIdx.x] = b4[threadIdx.x];
    __syncthreads();

    unsigned gid = blockIdx.x * blockDim.x + threadIdx.x;
    if (gid >= (unsigned)N_NODES * 2) return;
    int node = gid >> 1;
    int j    = gid & 1;

    float4 acc = agg_pull<2>(h, node, j);
    float dinv = node_dinv(node);
    float4 z;
    z.x = acc.x * dinv; z.y = acc.y * dinv; z.z = acc.z * dinv; z.w = acc.w * dinv;

    zsm[threadIdx.x] = z;
    __syncwarp();

    int gbase = threadIdx.x & ~1;
    float4 z0 = zsm[gbase + 0];
    float4 z1 = zsm[gbase + 1];
    float zf[8] = {z0.x, z0.y, z0.z, z0.w, z1.x, z1.y, z1.z, z1.w};

    int cbase = 32 * j;
    float4 s4[8];
    const float4* bsv = (const float4*)(bs + cbase);
#pragma unroll
    for (int q = 0; q < 8; q++) s4[q] = bsv[q];

#pragma unroll
    for (int k = 0; k < 8; k++) {
        float av = zf[k];
        const float4* wrow = (const float4*)(Ws + k * 64 + cbase);
#pragma unroll
        for (int q = 0; q < 8; q++) {
            float4 w = wrow[q];
            s4[q].x = fmaf(av, w.x, s4[q].x);
            s4[q].y = fmaf(av, w.y, s4[q].y);
            s4[q].z = fmaf(av, w.z, s4[q].z);
            s4[q].w = fmaf(av, w.w, s4[q].w);
        }
    }
    float4* outv = (float4*)(out + (size_t)node * 64 + cbase);
#pragma unroll
    for (int q = 0; q < 8; q++) outv[q] = s4[q];
}

// ---------------- launch ----------------
extern "C" void kernel_launch(void* const* d_in, const int* in_sizes, int n_in,
                              void* d_out, int out_size) {
    const float* x  = (const float*)d_in[0];
    const float* W1 = (const float*)d_in[2];
    const float* b1 = (const float*)d_in[3];
    const float* W2 = (const float*)d_in[4];
    const float* b2 = (const float*)d_in[5];
    const float* W3 = (const float*)d_in[6];
    const float* b3 = (const float*)d_in[7];
    const float* W4 = (const float*)d_in[8];
    const float* b4 = (const float*)d_in[9];
    float* out = (float*)d_out;

    float *A, *B;
    cudaGetSymbolAddress((void**)&A, g_bufA);
    cudaGetSymbolAddress((void**)&B, g_bufB);

    const int T = 256;

    // prep
    init_detect_kernel<<<cdiv(N_NODES, T), T>>>((const long long*)d_in[1]);
    prep_fill_kernel<<<cdiv(N_EDGES / 4, T), T>>>(d_in[1]);

    // conv1 gemm: A(fp16) = (x@W1)·dinv   (32-dim)
    gemm1_kernel<<<cdiv(N_NODES, 128), 128>>>(x, W1, (__half2*)A);
    // conv1 agg + conv2 gemm: B(fp16) = h2'  (16-dim)
    agg_gemm2_kernel<<<cdiv((long long)N_NODES * 8, T), T>>>(
        (const uint2*)A, (__half*)B, b1, W2);
    // conv2 agg + conv3 gemm: A(fp32) = h3'  (8-dim)
    agg_gemm3_kernel<<<cdiv((long long)N_NODES * 4, T), T>>>(
        (const uint2*)B, A, b2, W3);
    // conv3 agg + relu seed:  B(fp32) = h4'  (8-dim)
    agg_seed_kernel<<<cdiv((long long)N_NODES * 2, T), T>>>(
        (const float4*)A, (float4*)B, b3);
    // conv4 agg + final gemm: out (64-dim)
    agg_final_kernel<<<cdiv((long long)N_NODES * 2, T), T>>>(
        (const float4*)B, out, W4, b4);
}

// round 17
// speedup vs baseline: 1.0889x; 1.0111x over previous
#include <cuda_runtime.h>
#include <cuda_bf16.h>
#include <cuda_fp16.h>

// GCN: 4 layers, N=100000, dims 64->32->16->8->64, E=3,200,000.
// Factored norm; layer-4 linearity; pull-based padded CSR; GEMMs fused into
// agg epilogues. h1'/h2' stored fp16.  This rev: wide fp16 agg lanes
// (uint4 = 8 halfs per lane) + pairwise HADD2 tree -> ~2x fewer issue slots
// per byte (measured bottleneck: issue 55%, bandwidth only 4.8/11 TB/s).
//
// edge_index dtype detected on device (JAX silently downcasts int64->int32).

#define N_NODES 100000
#define N_EDGES 3200000
#define CAP     128

// ---------------- scratch ----------------
__device__ __align__(16) int   g_csr[(size_t)N_NODES * CAP];
__device__ __align__(16) int   g_cnt[N_NODES];
__device__ int                 g_is_i32;
__device__ __align__(16) float g_bufA[N_NODES * 32];
__device__ __align__(16) float g_bufB[N_NODES * 32];

static inline int cdiv(long long a, int b) { return (int)((a + b - 1) / b); }

__device__ __forceinline__ float node_dinv(int n) {
    return rsqrtf((float)g_cnt[n] + 1.0f);
}

// ---------------- prep ----------------
__global__ void init_detect_kernel(const long long* __restrict__ ei64) {
    unsigned i = blockIdx.x * blockDim.x + threadIdx.x;
    if (i < N_NODES) g_cnt[i] = 0;
    if (blockIdx.x == 0) {
        __shared__ int bad;
        if (threadIdx.x == 0) bad = 0;
        __syncthreads();
        for (int k = threadIdx.x; k < 2048; k += blockDim.x) {
            long long v = ei64[k];
            if (v < 0 || v >= N_NODES) bad = 1;
        }
        __syncthreads();
        if (threadIdx.x == 0) g_is_i32 = bad;
    }
}

__global__ void prep_fill_kernel(const void* __restrict__ ei_raw) {
    unsigned t = blockIdx.x * blockDim.x + threadIdx.x;
    unsigned e0 = t * 4;
    if (e0 >= N_EDGES) return;
    int s[4], d[4];
    if (g_is_i32) {
        const int* ei = (const int*)ei_raw;
        int4 sv = *(const int4*)(ei + e0);
        int4 dv = *(const int4*)(ei + N_EDGES + e0);
        s[0]=sv.x; s[1]=sv.y; s[2]=sv.z; s[3]=sv.w;
        d[0]=dv.x; d[1]=dv.y; d[2]=dv.z; d[3]=dv.w;
    } else {
        const long long* ei = (const long long*)ei_raw;
#pragma unroll
        for (int q = 0; q < 4; q++) {
            s[q] = (int)ei[e0 + q];
            d[q] = (int)ei[N_EDGES + e0 + q];
        }
    }
#pragma unroll
    for (int q = 0; q < 4; q++) {
        int ss = s[q] & 0x7fffffff; if (ss >= N_NODES) ss %= N_NODES;
        int dd = d[q] & 0x7fffffff; if (dd >= N_NODES) dd %= N_NODES;
        int slot = atomicAdd(&g_cnt[dd], 1);
        if (slot < CAP) g_csr[(size_t)dd * CAP + slot] = ss;
    }
}

// ---------------- gemm1: h1'(fp16) = (x@W1)·dinv  (64 -> 32) ----------
__global__ void gemm1_kernel(const float* __restrict__ in,
                             const float* __restrict__ W,
                             uint4* __restrict__ hout) {
    __shared__ float Ws[64 * 32];
    for (int i = threadIdx.x; i < 64 * 32; i += blockDim.x) Ws[i] = W[i];
    __syncthreads();

    int node = blockIdx.x * blockDim.x + threadIdx.x;
    if (node >= N_NODES) return;
    float dinv = node_dinv(node);

    float4 s4[8];
#pragma unroll
    for (int q = 0; q < 8; q++) s4[q] = make_float4(0.f, 0.f, 0.f, 0.f);

    const float4* row = (const float4*)(in + (size_t)node * 64);
    const float4* W4p = (const float4*)Ws;
#pragma unroll
    for (int c = 0; c < 16; c++) {
        float4 r = row[c];
        float a[4] = {r.x, r.y, r.z, r.w};
#pragma unroll
        for (int q = 0; q < 4; q++) {
            int k = 4 * c + q;
            float av = a[q];
#pragma unroll
            for (int jj = 0; jj < 8; jj++) {
                float4 w = W4p[k * 8 + jj];
                s4[jj].x = fmaf(av, w.x, s4[jj].x);
                s4[jj].y = fmaf(av, w.y, s4[jj].y);
                s4[jj].z = fmaf(av, w.z, s4[jj].z);
                s4[jj].w = fmaf(av, w.w, s4[jj].w);
            }
        }
    }
    __half2 hb[16];
#pragma unroll
    for (int q = 0; q < 8; q++) {
        hb[2 * q]     = __floats2half2_rn(s4[q].x * dinv, s4[q].y * dinv);
        hb[2 * q + 1] = __floats2half2_rn(s4[q].z * dinv, s4[q].w * dinv);
    }
    const uint4* hv = (const uint4*)hb;
#pragma unroll
    for (int q = 0; q < 4; q++) hout[(size_t)node * 4 + q] = hv[q];
}

// ---------------- fp16 helpers ----------------
__device__ __forceinline__ void cvt_add8(uint4 u, float4& a, float4& b) {
    float2 f0 = __half22float2(*(__half2*)&u.x);
    float2 f1 = __half22float2(*(__half2*)&u.y);
    float2 f2 = __half22float2(*(__half2*)&u.z);
    float2 f3 = __half22float2(*(__half2*)&u.w);
    a.x += f0.x; a.y += f0.y; a.z += f1.x; a.w += f1.y;
    b.x += f2.x; b.y += f2.y; b.z += f3.x; b.w += f3.y;
}

__device__ __forceinline__ uint4 hadd2x4(uint4 p, uint4 q) {
    uint4 r;
    __half2 h;
    h = __hadd2(*(__half2*)&p.x, *(__half2*)&q.x); r.x = *(unsigned*)&h;
    h = __hadd2(*(__half2*)&p.y, *(__half2*)&q.y); r.y = *(unsigned*)&h;
    h = __hadd2(*(__half2*)&p.z, *(__half2*)&q.z); r.z = *(unsigned*)&h;
    h = __hadd2(*(__half2*)&p.w, *(__half2*)&q.w); r.w = *(unsigned*)&h;
    return r;
}

// fp16 agg core: lane covers 8 halfs (uint4). U4PR = uint4 per row.
template <int U4PR>
__device__ __forceinline__ void agg_pull_h8(const uint4* __restrict__ h,
                                            int node, int j,
                                            float4& accA, float4& accB) {
    accA = make_float4(0.f, 0.f, 0.f, 0.f);
    accB = make_float4(0.f, 0.f, 0.f, 0.f);
    cvt_add8(h[(size_t)node * U4PR + j], accA, accB);   // self loop
    int n = g_cnt[node];
    if (n > CAP) n = CAP;
    const int* lst = g_csr + (size_t)node * CAP;
    int i = 0;
    for (; i + 4 <= n; i += 4) {
        int4 a4 = *(const int4*)(lst + i);
        uint4 u0 = h[(size_t)a4.x * U4PR + j];
        uint4 u1 = h[(size_t)a4.y * U4PR + j];
        uint4 u2 = h[(size_t)a4.z * U4PR + j];
        uint4 u3 = h[(size_t)a4.w * U4PR + j];
        uint4 s = hadd2x4(hadd2x4(u0, u1), hadd2x4(u2, u3));  // fp16 tree
        cvt_add8(s, accA, accB);
    }
    for (; i < n; i++)
        cvt_add8(h[(size_t)__ldg(&lst[i]) * U4PR + j], accA, accB);
}

// fp32 agg core (TPE float4 per row)
template <int TPE>
__device__ __forceinline__ float4 agg_pull(const float4* __restrict__ h,
                                           int node, int j) {
    float4 acc = h[(size_t)node * TPE + j];
    int n = g_cnt[node];
    if (n > CAP) n = CAP;
    const int* lst = g_csr + (size_t)node * CAP;
    int i = 0;
    for (; i + 4 <= n; i += 4) {
        int4 a4 = *(const int4*)(lst + i);
        float4 v0 = h[(size_t)a4.x * TPE + j];
        float4 v1 = h[(size_t)a4.y * TPE + j];
        float4 v2 = h[(size_t)a4.z * TPE + j];
        float4 v3 = h[(size_t)a4.w * TPE + j];
        acc.x += (v0.x + v1.x) + (v2.x + v3.x);
        acc.y += (v0.y + v1.y) + (v2.y + v3.y);
        acc.z += (v0.z + v1.z) + (v2.z + v3.z);
        acc.w += (v0.w + v1.w) + (v2.w + v3.w);
    }
    for (; i < n; i++) {
        int s = __ldg(&lst[i]);
        float4 v = h[(size_t)s * TPE + j];
        acc.x += v.x; acc.y += v.y; acc.z += v.z; acc.w += v.w;
    }
    return acc;
}

// ---- agg32(fp16,4 lanes) + gemm2: h2'(fp16) = relu(Agg·dinv+b1)@W2·dinv ----
__global__ void agg_gemm2_kernel(const uint4* __restrict__ h,
                                 __half* __restrict__ h2,
                                 const float* __restrict__ b1,
                                 const float* __restrict__ W2) {
    __shared__ float Ws[32 * 16];
    __shared__ float bs[32];
    __shared__ float4 zsm[512];
    for (int i = threadIdx.x; i < 32 * 16; i += blockDim.x) Ws[i] = W2[i];
    if (threadIdx.x < 32) bs[threadIdx.x] = b1[threadIdx.x];
    __syncthreads();

    unsigned gid = blockIdx.x * blockDim.x + threadIdx.x;
    if (gid >= (unsigned)N_NODES * 4) return;      // 400000 % 32 == 0
    int node = gid >> 2;
    int j    = gid & 3;                            // halfs [8j, 8j+8)

    float4 accA, accB;
    agg_pull_h8<4>(h, node, j, accA, accB);
    float dinv = node_dinv(node);
    const float* bj = bs + 8 * j;
    float4 zA, zB;
    zA.x = fmaxf(fmaf(accA.x, dinv, bj[0]), 0.f);
    zA.y = fmaxf(fmaf(accA.y, dinv, bj[1]), 0.f);
    zA.z = fmaxf(fmaf(accA.z, dinv, bj[2]), 0.f);
    zA.w = fmaxf(fmaf(accA.w, dinv, bj[3]), 0.f);
    zB.x = fmaxf(fmaf(accB.x, dinv, bj[4]), 0.f);
    zB.y = fmaxf(fmaf(accB.y, dinv, bj[5]), 0.f);
    zB.z = fmaxf(fmaf(accB.z, dinv, bj[6]), 0.f);
    zB.w = fmaxf(fmaf(accB.w, dinv, bj[7]), 0.f);

    zsm[2 * threadIdx.x]     = zA;                 // STS.128 x2
    zsm[2 * threadIdx.x + 1] = zB;
    __syncwarp();

    int gbase = threadIdx.x & ~3;                  // 4 lanes per node
    int c = 4 * j;                                 // lane's 4 output cols
    float4 o = make_float4(0.f, 0.f, 0.f, 0.f);
#pragma unroll
    for (int v = 0; v < 8; v++) {                  // k = 4v..4v+3
        float4 zv = zsm[2 * gbase + v];
        const float* wr = Ws + (4 * v) * 16 + c;
        float4 w0 = *(const float4*)(wr);
        float4 w1 = *(const float4*)(wr + 16);
        float4 w2 = *(const float4*)(wr + 32);
        float4 w3 = *(const float4*)(wr + 48);
        o.x = fmaf(zv.x, w0.x, o.x); o.y = fmaf(zv.x, w0.y, o.y);
        o.z = fmaf(zv.x, w0.z, o.z); o.w = fmaf(zv.x, w0.w, o.w);
        o.x = fmaf(zv.y, w1.x, o.x); o.y = fmaf(zv.y, w1.y, o.y);
        o.z = fmaf(zv.y, w1.z, o.z); o.w = fmaf(zv.y, w1.w, o.w);
        o.x = fmaf(zv.z, w2.x, o.x); o.y = fmaf(zv.z, w2.y, o.y);
        o.z = fmaf(zv.z, w2.z, o.z); o.w = fmaf(zv.z, w2.w, o.w);
        o.x = fmaf(zv.w, w3.x, o.x); o.y = fmaf(zv.w, w3.y, o.y);
        o.z = fmaf(zv.w, w3.z, o.z); o.w = fmaf(zv.w, w3.w, o.w);
    }
    __half2 p0 = __floats2half2_rn(o.x * dinv, o.y * dinv);
    __half2 p1 = __floats2half2_rn(o.z * dinv, o.w * dinv);
    uint2 pv;
    pv.x = *(unsigned*)&p0; pv.y = *(unsigned*)&p1;
    *(uint2*)(h2 + (size_t)node * 16 + c) = pv;
}

// ---- agg16(fp16,2 lanes) + gemm3: h3'(fp32) = relu(Agg·dinv+b2)@W3·dinv ----
__global__ void agg_gemm3_kernel(const uint4* __restrict__ h,
                                 float* __restrict__ h3,
                                 const float* __restrict__ b2,
                                 const float* __restrict__ W3) {
    __shared__ float Ws[16 * 8];
    __shared__ float bs[16];
    __shared__ float4 zsm[512];
    for (int i = threadIdx.x; i < 16 * 8; i += blockDim.x) Ws[i] = W3[i];
    if (threadIdx.x < 16) bs[threadIdx.x] = b2[threadIdx.x];
    __syncthreads();

    unsigned gid = blockIdx.x * blockDim.x + threadIdx.x;
    if (gid >= (unsigned)N_NODES * 2) return;      // 200000 % 32 == 0
    int node = gid >> 1;
    int j    = gid & 1;                            // halfs [8j, 8j+8)

    float4 accA, accB;
    agg_pull_h8<2>(h, node, j, accA, accB);
    float dinv = node_dinv(node);
    const float* bj = bs + 8 * j;
    float4 zA, zB;
    zA.x = fmaxf(fmaf(accA.x, dinv, bj[0]), 0.f);
    zA.y = fmaxf(fmaf(accA.y, dinv, bj[1]), 0.f);
    zA.z = fmaxf(fmaf(accA.z, dinv, bj[2]), 0.f);
    zA.w = fmaxf(fmaf(accA.w, dinv, bj[3]), 0.f);
    zB.x = fmaxf(fmaf(accB.x, dinv, bj[4]), 0.f);
    zB.y = fmaxf(fmaf(accB.y, dinv, bj[5]), 0.f);
    zB.z = fmaxf(fmaf(accB.z, dinv, bj[6]), 0.f);
    zB.w = fmaxf(fmaf(accB.w, dinv, bj[7]), 0.f);

    zsm[2 * threadIdx.x]     = zA;
    zsm[2 * threadIdx.x + 1] = zB;
    __syncwarp();

    int gbase = threadIdx.x & ~1;                  // 2 lanes per node
    int c = 4 * j;                                 // lane's 4 output cols
    float4 o = make_float4(0.f, 0.f, 0.f, 0.f);
#pragma unroll
    for (int v = 0; v < 4; v++) {                  // k = 4v..4v+3
        float4 zv = zsm[2 * gbase + v];
        const float* wr = Ws + (4 * v) * 8 + c;
        float4 w0 = *(const float4*)(wr);
        float4 w1 = *(const float4*)(wr + 8);
        float4 w2 = *(const float4*)(wr + 16);
        float4 w3 = *(const float4*)(wr + 24);
        o.x = fmaf(zv.x, w0.x, o.x); o.y = fmaf(zv.x, w0.y, o.y);
        o.z = fmaf(zv.x, w0.z, o.z); o.w = fmaf(zv.x, w0.w, o.w);
        o.x = fmaf(zv.y, w1.x, o.x); o.y = fmaf(zv.y, w1.y, o.y);
        o.z = fmaf(zv.y, w1.z, o.z); o.w = fmaf(zv.y, w1.w, o.w);
        o.x = fmaf(zv.z, w2.x, o.x); o.y = fmaf(zv.z, w2.y, o.y);
        o.z = fmaf(zv.z, w2.z, o.z); o.w = fmaf(zv.z, w2.w, o.w);
        o.x = fmaf(zv.w, w3.x, o.x); o.y = fmaf(zv.w, w3.y, o.y);
        o.z = fmaf(zv.w, w3.z, o.z); o.w = fmaf(zv.w, w3.w, o.w);
    }
    o.x *= dinv; o.y *= dinv; o.z *= dinv; o.w *= dinv;
    *(float4*)(h3 + (size_t)node * 8 + c) = o;
}

// ---- agg8 + seed: h4' = relu(Agg(h3')·dinv + b3) · dinv  (fp32) ----
__global__ void agg_seed_kernel(const float4* __restrict__ h,
                                float4* __restrict__ h4,
                                const float* __restrict__ b3) {
    unsigned gid = blockIdx.x * blockDim.x + threadIdx.x;
    if (gid >= (unsigned)N_NODES * 2) return;
    int node = gid >> 1;
    int j    = gid & 1;

    float4 acc = agg_pull<2>(h, node, j);
    float dinv = node_dinv(node);
    float4 bv = *(const float4*)(b3 + 4 * j);
    float4 o;
    o.x = fmaxf(fmaf(acc.x, dinv, bv.x), 0.f) * dinv;
    o.y = fmaxf(fmaf(acc.y, dinv, bv.y), 0.f) * dinv;
    o.z = fmaxf(fmaf(acc.z, dinv, bv.z), 0.f) * dinv;
    o.w = fmaxf(fmaf(acc.w, dinv, bv.w), 0.f) * dinv;
    h4[gid] = o;
}

// ---- agg8 + gemm4: out = (Agg(h4')·dinv)@W4 + b4 ----
__global__ void agg_final_kernel(const float4* __restrict__ h,
                                 float* __restrict__ out,
                                 const float* __restrict__ W4,
                                 const float* __restrict__ b4) {
    __shared__ float Ws[8 * 64];
    __shared__ float bs[64];
    __shared__ float4 zsm[256];
    for (int i = threadIdx.x; i < 8 * 64; i += blockDim.x) Ws[i] = W4[i];
    if (threadIdx.x < 64) bs[threadIdx.x] = b4[threadIdx.x];
    __syncthreads();

    unsigned gid = blockIdx.x * blockDim.x + threadIdx.x;
    if (gid >= (unsigned)N_NODES * 2) return;
    int node = gid >> 1;
    int j    = gid & 1;

    float4 acc = agg_pull<2>(h, node, j);
    float dinv = node_dinv(node);
    float4 z;
    z.x = acc.x * dinv; z.y = acc.y * dinv; z.z = acc.z * dinv; z.w = acc.w * dinv;

    zsm[threadIdx.x] = z;
    __syncwarp();

    int gbase = threadIdx.x & ~1;
    float4 z0 = zsm[gbase + 0];
    float4 z1 = zsm[gbase + 1];
    float zf[8] = {z0.x, z0.y, z0.z, z0.w, z1.x, z1.y, z1.z, z1.w};

    int cbase = 32 * j;
    float4 s4[8];
    const float4* bsv = (const float4*)(bs + cbase);
#pragma unroll
    for (int q = 0; q < 8; q++) s4[q] = bsv[q];

#pragma unroll
    for (int k = 0; k < 8; k++) {
        float av = zf[k];
        const float4* wrow = (const float4*)(Ws + k * 64 + cbase);
#pragma unroll
        for (int q = 0; q < 8; q++) {
            float4 w = wrow[q];
            s4[q].x = fmaf(av, w.x, s4[q].x);
            s4[q].y = fmaf(av, w.y, s4[q].y);
            s4[q].z = fmaf(av, w.z, s4[q].z);
            s4[q].w = fmaf(av, w.w, s4[q].w);
        }
    }
    float4* outv = (float4*)(out + (size_t)node * 64 + cbase);
#pragma unroll
    for (int q = 0; q < 8; q++) outv[q] = s4[q];
}

// ---------------- launch ----------------
extern "C" void kernel_launch(void* const* d_in, const int* in_sizes, int n_in,
                              void* d_out, int out_size) {
    const float* x  = (const float*)d_in[0];
    const float* W1 = (const float*)d_in[2];
    const float* b1 = (const float*)d_in[3];
    const float* W2 = (const float*)d_in[4];
    const float* b2 = (const float*)d_in[5];
    const float* W3 = (const float*)d_in[6];
    const float* b3 = (const float*)d_in[7];
    const float* W4 = (const float*)d_in[8];
    const float* b4 = (const float*)d_in[9];
    float* out = (float*)d_out;

    float *A, *B;
    cudaGetSymbolAddress((void**)&A, g_bufA);
    cudaGetSymbolAddress((void**)&B, g_bufB);

    const int T = 256;

    init_detect_kernel<<<cdiv(N_NODES, T), T>>>((const long long*)d_in[1]);
    prep_fill_kernel<<<cdiv(N_EDGES / 4, T), T>>>(d_in[1]);

    // conv1 gemm: A(fp16, 4 uint4/row) = (x@W1)·dinv
    gemm1_kernel<<<cdiv(N_NODES, 128), 128>>>(x, W1, (uint4*)A);
    // conv1 agg + conv2 gemm: B(fp16, 2 uint4/row) = h2'
    agg_gemm2_kernel<<<cdiv((long long)N_NODES * 4, T), T>>>(
        (const uint4*)A, (__half*)B, b1, W2);
    // conv2 agg + conv3 gemm: A(fp32, 8 floats/row) = h3'
    agg_gemm3_kernel<<<cdiv((long long)N_NODES * 2, T), T>>>(
        (const uint4*)B, A, b2, W3);
    // conv3 agg + relu seed:  B(fp32) = h4'
    agg_seed_kernel<<<cdiv((long long)N_NODES * 2, T), T>>>(
        (const float4*)A, (float4*)B, b3);
    // conv4 agg + final gemm: out (64-dim)
    agg_final_kernel<<<cdiv((long long)N_NODES * 2, T), T>>>(
        (const float4*)B, out, W4, b4);
}